// round 4
// baseline (speedup 1.0000x reference)
#include <cuda_runtime.h>

// Problem constants
#define BB   256
#define TTOT 16384
#define ALPHA_F 0.95f

// LIF chunking: 128 chunks of 128, warm-up 512 (verified exact)
#define LCHUNK 128
#define WARM   512
#define NCHUNK (TTOT / LCHUNK)   // 128

// lif smem tiling: tile = [3ch][32 t][256 b], column-padded to 257
#define TTILE   32
#define BPAD    257
#define CHPLANE (TTILE * BPAD)          // 8224 floats
#define BUFSZ   (3 * CHPLANE)           // 24672 floats = 98688 B
#define LIF_SMEM_BYTES (2 * BUFSZ * 4)  // 197376 B (two tile buffers)

// ---------------------------------------------------------------------------
// Kernel 1: causal conv, 3 branches (k = 8, 16, 32), scaled by 1/sqrt(k).
// ---------------------------------------------------------------------------
__global__ __launch_bounds__(512) void conv_kernel(
    const float* __restrict__ x,
    const float* __restrict__ w0,
    const float* __restrict__ w1,
    const float* __restrict__ w2,
    float* __restrict__ u)
{
    __shared__ float xs[2080];      // 31 halo + 2048 tile (+1 pad)

    const int b    = blockIdx.x;    // 0..255
    const int tile = blockIdx.y;    // 0..7
    const int t0   = tile * 2048;
    const float* xb = x + (size_t)b * TTOT;

    for (int i = threadIdx.x; i < 2080; i += 512) {
        int gi = t0 + i - 31;
        xs[i] = (gi >= 0 && gi < TTOT) ? xb[gi] : 0.0f;
    }

    float W2[32], W1[16], W0[8];
#pragma unroll
    for (int i = 0; i < 32; i++) W2[i] = w2[i] * 0.1767766952966369f;   // 1/sqrt(32)
#pragma unroll
    for (int i = 0; i < 16; i++) W1[i] = w1[i] * 0.25f;                 // 1/sqrt(16)
#pragma unroll
    for (int i = 0; i < 8;  i++) W0[i] = w0[i] * 0.3535533905932738f;   // 1/sqrt(8)

    __syncthreads();

    const int tt0 = threadIdx.x * 4;

    float xv[36];
#pragma unroll
    for (int q = 0; q < 9; q++) {
        float4 v = *reinterpret_cast<const float4*>(&xs[tt0 + 4 * q]);
        xv[4 * q + 0] = v.x; xv[4 * q + 1] = v.y;
        xv[4 * q + 2] = v.z; xv[4 * q + 3] = v.w;
    }

    float a0[4] = {0.f, 0.f, 0.f, 0.f};
    float a1[4] = {0.f, 0.f, 0.f, 0.f};
    float a2[4] = {0.f, 0.f, 0.f, 0.f};

#pragma unroll
    for (int kk = 0; kk < 32; kk++)
#pragma unroll
        for (int r = 0; r < 4; r++)
            a2[r] = fmaf(W2[kk], xv[kk + r], a2[r]);
#pragma unroll
    for (int kk = 0; kk < 16; kk++)
#pragma unroll
        for (int r = 0; r < 4; r++)
            a1[r] = fmaf(W1[kk], xv[16 + kk + r], a1[r]);
#pragma unroll
    for (int kk = 0; kk < 8; kk++)
#pragma unroll
        for (int r = 0; r < 4; r++)
            a0[r] = fmaf(W0[kk], xv[24 + kk + r], a0[r]);

    const int t = t0 + tt0;
    float* ub = u + (size_t)b * 3 * TTOT;
    *reinterpret_cast<float4*>(ub + 0 * TTOT + t) = make_float4(a0[0], a0[1], a0[2], a0[3]);
    *reinterpret_cast<float4*>(ub + 1 * TTOT + t) = make_float4(a1[0], a1[1], a1[2], a1[3]);
    *reinterpret_cast<float4*>(ub + 2 * TTOT + t) = make_float4(a2[0], a2[1], a2[2], a2[3]);
}

// ---------------------------------------------------------------------------
// Kernel 2: LIF + WTA scan. Block = 256 threads = one chunk x 256 batches.
// Grid = 128 chunks. Double-buffered smem tiles [3][32][257]; spikes are
// written in place over consumed u slots, drained coalesced per tile.
//
// Staging map (ch-major rows so STS banks 4o+b+k are all distinct per warp):
//   idx = (h*12 + j)*256 + tid ; o = idx&7 ; row = idx>>3 ;
//   ch = row>>8 ; b = row&255
//   global: u[(b*3+ch)*TTOT + t0 + 4o .. +3]   (4 full 128B lines / warp-op)
//   smem:   buf[ch*CHPLANE + (4o+k)*BPAD + b]
// ---------------------------------------------------------------------------
__global__ __launch_bounds__(256) void lif_kernel(
    const float* __restrict__ u,
    float* __restrict__ s)
{
    extern __shared__ float sm[];
    float* buf0 = sm;
    float* buf1 = sm + BUFSZ;

    const int tid = threadIdx.x;
    const int c   = blockIdx.x;            // chunk 0..127

    const int commit = c * LCHUNK;
    int start = commit - WARM; if (start < 0) start = 0;
    const int end    = commit + LCHUNK;
    const int ntiles = (end - start) >> 5;

#define LD_BATCH(t0v, h, pf)                                                   \
    {                                                                          \
        _Pragma("unroll")                                                      \
        for (int j = 0; j < 12; j++) {                                         \
            int idx = ((h) * 12 + j) * 256 + tid;                              \
            int o   = idx & 7;                                                 \
            int row = idx >> 3;                                                \
            int ch  = row >> 8;                                                \
            int b   = row & 255;                                               \
            const float* g = u + ((size_t)(b * 3 + ch)) * TTOT + (t0v) + 4 * o;\
            pf[j] = *reinterpret_cast<const float4*>(g);                       \
        }                                                                      \
    }
#define ST_BATCH(dst, h, pf)                                                   \
    {                                                                          \
        _Pragma("unroll")                                                      \
        for (int j = 0; j < 12; j++) {                                         \
            int idx = ((h) * 12 + j) * 256 + tid;                              \
            int o   = idx & 7;                                                 \
            int row = idx >> 3;                                                \
            int ch  = row >> 8;                                                \
            int b   = row & 255;                                               \
            float* p = (dst) + ch * CHPLANE + (4 * o) * BPAD + b;              \
            p[0 * BPAD] = pf[j].x;                                             \
            p[1 * BPAD] = pf[j].y;                                             \
            p[2 * BPAD] = pf[j].z;                                             \
            p[3 * BPAD] = pf[j].w;                                             \
        }                                                                      \
    }

    // prime tile 0 into buf0
    {
        float4 pa[12], pb[12];
        LD_BATCH(start, 0, pa);
        LD_BATCH(start, 1, pb);
        ST_BATCH(buf0, 0, pa);
        ST_BATCH(buf0, 1, pb);
    }
    __syncthreads();

    float y0 = 0.f, y1 = 0.f, y2 = 0.f;

    for (int i = 0; i < ntiles; i++) {
        const int t0 = start + i * TTILE;
        float* Bc = (i & 1) ? buf1 : buf0;
        float* Bn = (i & 1) ? buf0 : buf1;
        const bool has_next  = (i + 1 < ntiles);
        const bool is_commit = (t0 >= commit);

        float4 pf[12];
        if (has_next) LD_BATCH(t0 + TTILE, 0, pf);

#pragma unroll
        for (int t = 0; t < 16; t++) {
            float* p0 = Bc + 0 * CHPLANE + t * BPAD + tid;
            float* p1 = Bc + 1 * CHPLANE + t * BPAD + tid;
            float* p2 = Bc + 2 * CHPLANE + t * BPAD + tid;
            const float w0 = fmaf(ALPHA_F, y0, *p0);
            const float w1 = fmaf(ALPHA_F, y1, *p1);
            const float w2 = fmaf(ALPHA_F, y2, *p2);
            const bool g01 = (w0 >= w1), g02 = (w0 >= w2), g12 = (w1 >= w2);
            const bool f0 = g01 & g02 & (w0 >= 1.0f);
            const bool f1 = (!g01) & g12 & (w1 >= 1.0f);
            const bool f2 = (!g02) & (!g12) & (w2 >= 1.0f);
            const float a  = f0 ? 1.0f : 0.0f;
            const float bb = f1 ? 1.0f : 0.0f;
            const float cc = f2 ? 1.0f : 0.0f;
            y0 = w0 - a; y1 = w1 - bb; y2 = w2 - cc;
            if (is_commit) { *p0 = a; *p1 = bb; *p2 = cc; }   // in-place spike
        }

        if (has_next) {
            ST_BATCH(Bn, 0, pf);           // LDGs issued ~16 steps ago: covered
            LD_BATCH(t0 + TTILE, 1, pf);
        }

#pragma unroll
        for (int t = 16; t < 32; t++) {
            float* p0 = Bc + 0 * CHPLANE + t * BPAD + tid;
            float* p1 = Bc + 1 * CHPLANE + t * BPAD + tid;
            float* p2 = Bc + 2 * CHPLANE + t * BPAD + tid;
            const float w0 = fmaf(ALPHA_F, y0, *p0);
            const float w1 = fmaf(ALPHA_F, y1, *p1);
            const float w2 = fmaf(ALPHA_F, y2, *p2);
            const bool g01 = (w0 >= w1), g02 = (w0 >= w2), g12 = (w1 >= w2);
            const bool f0 = g01 & g02 & (w0 >= 1.0f);
            const bool f1 = (!g01) & g12 & (w1 >= 1.0f);
            const bool f2 = (!g02) & (!g12) & (w2 >= 1.0f);
            const float a  = f0 ? 1.0f : 0.0f;
            const float bb = f1 ? 1.0f : 0.0f;
            const float cc = f2 ? 1.0f : 0.0f;
            y0 = w0 - a; y1 = w1 - bb; y2 = w2 - cc;
            if (is_commit) { *p0 = a; *p1 = bb; *p2 = cc; }
        }

        if (has_next) ST_BATCH(Bn, 1, pf);
        __syncthreads();   // Bn staged; Bc reads + in-place spike writes done

        if (is_commit) {
            // coalesced spike drain from Bc (same map as staging)
#pragma unroll
            for (int q = 0; q < 24; q++) {
                int idx = q * 256 + tid;
                int o   = idx & 7;
                int row = idx >> 3;
                int ch  = row >> 8;
                int b   = row & 255;
                const float* p = Bc + ch * CHPLANE + (4 * o) * BPAD + b;
                float4 v = make_float4(p[0], p[BPAD], p[2 * BPAD], p[3 * BPAD]);
                float* g = s + ((size_t)(b * 3 + ch)) * TTOT + t0 + 4 * o;
                *reinterpret_cast<float4*>(g) = v;
            }
            __syncthreads();   // Bc drained before tile i+1 restages it
        }
    }
#undef LD_BATCH
#undef ST_BATCH
}

// ---------------------------------------------------------------------------
// Launch. Inputs: x [256*16384], w0 [8], w1 [16], w2 [32], y (unused).
// Output: concat(u, s_all), both [256, 3, 16384] float32.
// ---------------------------------------------------------------------------
extern "C" void kernel_launch(void* const* d_in, const int* in_sizes, int n_in,
                              void* d_out, int out_size)
{
    const float* x  = (const float*)d_in[0];
    const float* w0 = (const float*)d_in[1];
    const float* w1 = (const float*)d_in[2];
    const float* w2 = (const float*)d_in[3];

    float* u = (float*)d_out;
    float* s = u + (size_t)BB * 3 * TTOT;

    cudaFuncSetAttribute(lif_kernel, cudaFuncAttributeMaxDynamicSharedMemorySize,
                         LIF_SMEM_BYTES);

    dim3 cgrid(BB, TTOT / 2048);
    conv_kernel<<<cgrid, 512>>>(x, w0, w1, w2, u);

    lif_kernel<<<NCHUNK, 256, LIF_SMEM_BYTES>>>(u, s);
}